// round 2
// baseline (speedup 1.0000x reference)
#include <cuda_runtime.h>

// LogLinearAttention — algebraic collapse:
//   softmax over axis=1 (query axis) followed by sum over axis=1 makes the
//   attention weights sum to exactly 1 per column t, so
//     pooled[b,d] = sum_t r[b,t,d] = xsum[b,:]·Wr[d,:] + S*br[d]
//     out[b] = sigmoid( xsum[b,:]·c + S*(br·Wl) + bl ),  c[e] = sum_d Wl[d]*Wr[d,e]
//   q/v projections and their weights are dead.

#define BB 8
#define SS 2048
#define DD 512
#define NS 32                 // s-splits for the x reduction
#define ROWS_PER (SS / NS)    // 64 rows per block
#define CBLKS 4               // blocks computing c[]

__device__ float g_partials[BB * NS * DD];  // per-(b, s-chunk) partial row sums
__device__ float g_c[DD];                   // c[e] = sum_d Wl[d]*Wr[d*DD+e]

// K1: 256 blocks reduce x over s into partials; 4 extra blocks compute c.
// 128 threads/block; each thread owns one float4 lane of D=512.
__global__ void __launch_bounds__(128) k_reduce_and_c(
    const float* __restrict__ x,
    const float* __restrict__ Wr,
    const float* __restrict__ Wl)
{
    const int blk = blockIdx.x;
    const int tid = threadIdx.x;

    if (blk < BB * NS) {
        const int b  = blk / NS;
        const int sc = blk % NS;
        const float4* xp =
            reinterpret_cast<const float4*>(x + ((size_t)b * SS + (size_t)sc * ROWS_PER) * DD) + tid;
        float4 acc = make_float4(0.f, 0.f, 0.f, 0.f);
#pragma unroll 8
        for (int s = 0; s < ROWS_PER; ++s) {
            float4 v = xp[(size_t)s * (DD / 4)];
            acc.x += v.x; acc.y += v.y; acc.z += v.z; acc.w += v.w;
        }
        reinterpret_cast<float4*>(g_partials + (size_t)blk * DD)[tid] = acc;
    } else {
        // c[e] = sum_d Wl[d] * Wr[d, e]   (Wr row-major [D, D])
        const int j = blk - BB * NS;      // 0..3
        const int e = j * 128 + tid;      // this thread's output column

        // stage Wl into shared once (broadcast-friendly loop after)
        __shared__ float s_wl[DD];
#pragma unroll
        for (int i = tid; i < DD; i += 128) s_wl[i] = Wl[i];
        __syncthreads();

        float acc = 0.f;
#pragma unroll 8
        for (int d = 0; d < DD; ++d) {
            acc += s_wl[d] * __ldg(&Wr[(size_t)d * DD + e]);
        }
        g_c[e] = acc;
    }
}

// K2: one block per batch element. Reduce the NS partials, dot with c,
// fold in S*(br·Wl) + bl, sigmoid.
__global__ void __launch_bounds__(128) k_finish(
    const float* __restrict__ br,
    const float* __restrict__ Wl,
    const float* __restrict__ bl,
    float* __restrict__ out)
{
    const int b   = blockIdx.x;
    const int tid = threadIdx.x;   // 128 threads, each owns 4 of D=512

    float4 acc = make_float4(0.f, 0.f, 0.f, 0.f);
    const float4* pp = reinterpret_cast<const float4*>(g_partials + (size_t)b * NS * DD) + tid;
#pragma unroll
    for (int p = 0; p < NS; ++p) {
        float4 v = pp[(size_t)p * (DD / 4)];
        acc.x += v.x; acc.y += v.y; acc.z += v.z; acc.w += v.w;
    }

    const float4 c4  = reinterpret_cast<const float4*>(g_c)[tid];
    const float4 br4 = reinterpret_cast<const float4*>(br)[tid];
    const float4 wl4 = reinterpret_cast<const float4*>(Wl)[tid];

    float val = acc.x * c4.x + acc.y * c4.y + acc.z * c4.z + acc.w * c4.w
              + (float)SS * (br4.x * wl4.x + br4.y * wl4.y + br4.z * wl4.z + br4.w * wl4.w);

    __shared__ float sdata[128];
    sdata[tid] = val;
    __syncthreads();
#pragma unroll
    for (int off = 64; off > 0; off >>= 1) {
        if (tid < off) sdata[tid] += sdata[tid + off];
        __syncthreads();
    }
    if (tid == 0) {
        float z = sdata[0] + bl[0];
        out[b] = 1.0f / (1.0f + expf(-z));
    }
}

extern "C" void kernel_launch(void* const* d_in, const int* in_sizes, int n_in,
                              void* d_out, int out_size)
{
    // metadata order: x, Wq, bq, Wv, bv, Wr, br, Wl, bl
    const float* x  = (const float*)d_in[0];
    const float* Wr = (const float*)d_in[5];
    const float* br = (const float*)d_in[6];
    const float* Wl = (const float*)d_in[7];
    const float* bl = (const float*)d_in[8];
    float* out = (float*)d_out;

    k_reduce_and_c<<<BB * NS + CBLKS, 128>>>(x, Wr, Wl);
    k_finish<<<BB, 128>>>(br, Wl, bl, out);
}

// round 3
// speedup vs baseline: 1.2897x; 1.2897x over previous
#include <cuda_runtime.h>

// LogLinearAttention — algebraic collapse (verified exact in R1, rel_err=0):
//   softmax over axis=1 followed by sum over axis=1 => column weights sum to 1:
//     pooled[b,:] = sum_t r[b,t,:]  =>  out[b] = sigmoid( xsum[b,:]·c + S*(br·Wl) + bl )
//   with xsum[b,e] = sum_s x[b,s,e],  c[e] = sum_d Wl[d]*Wr[d,e].
//   q/v projections and their weights are dead.
//
// R2: parallelism fix. K1: 1024 reduce blocks (MLP=16/thread) + 16 c-partial
// blocks (d-split, MLP=32/thread). K2: 8 blocks x 1024 threads, 8 sub-reducers
// per float4 lane. Everything fp32, deterministic, allocation-free.

#define BB 8
#define SS 2048
#define DD 512
#define NS 128                    // s-splits for the x reduction
#define ROWS_PER (SS / NS)        // 16 rows per block
#define CBLKS 16                  // d-split blocks for c partials
#define DCHUNK (DD / CBLKS)       // 32 d-rows per c-block
#define PSUB 8                    // sub-reducers per lane in K2
#define PPS (NS / PSUB)           // 16 partials per sub-reducer

__device__ float g_partials[BB * NS * DD];   // per-(b, s-chunk) partial row sums (2 MB)
__device__ float g_cpart[CBLKS * DD];        // partial c over d-chunks

// K1: 1024 blocks reduce x over s; 16 extra blocks compute c partials.
__global__ void __launch_bounds__(128) k_reduce_and_c(
    const float* __restrict__ x,
    const float* __restrict__ Wr,
    const float* __restrict__ Wl)
{
    const int blk = blockIdx.x;
    const int tid = threadIdx.x;   // 128 threads = one float4 lane each (D=512)

    if (blk < BB * NS) {
        const int b  = blk / NS;
        const int sc = blk % NS;
        const float4* xp =
            reinterpret_cast<const float4*>(x + ((size_t)b * SS + (size_t)sc * ROWS_PER) * DD) + tid;
        float4 acc = make_float4(0.f, 0.f, 0.f, 0.f);
#pragma unroll
        for (int s = 0; s < ROWS_PER; ++s) {            // 16 independent loads, MLP=16
            float4 v = xp[(size_t)s * (DD / 4)];
            acc.x += v.x; acc.y += v.y; acc.z += v.z; acc.w += v.w;
        }
        reinterpret_cast<float4*>(g_partials + (size_t)blk * DD)[tid] = acc;
    } else {
        // c partial: block j covers d in [j*32, j*32+32), all 512 e columns.
        const int j = blk - BB * NS;
        __shared__ float s_wl[DCHUNK];
        if (tid < DCHUNK) s_wl[tid] = Wl[j * DCHUNK + tid];
        __syncthreads();

        const float4* wr =
            reinterpret_cast<const float4*>(Wr + (size_t)j * DCHUNK * DD) + tid;
        float4 acc = make_float4(0.f, 0.f, 0.f, 0.f);
#pragma unroll
        for (int d = 0; d < DCHUNK; ++d) {              // 32 independent loads, MLP=32
            float4 w = wr[(size_t)d * (DD / 4)];
            float wl = s_wl[d];
            acc.x += wl * w.x; acc.y += wl * w.y; acc.z += wl * w.z; acc.w += wl * w.w;
        }
        reinterpret_cast<float4*>(g_cpart)[(size_t)j * (DD / 4) + tid] = acc;
    }
}

// K2: one block per batch element, 1024 threads.
// tid = psub*128 + lane: lane owns one float4 column, psub splits the NS
// partials 8 ways. Dot with (folded) c, add bias term once per lane, reduce.
__global__ void __launch_bounds__(1024) k_finish(
    const float* __restrict__ br,
    const float* __restrict__ Wl,
    const float* __restrict__ bl,
    float* __restrict__ out)
{
    const int b    = blockIdx.x;
    const int tid  = threadIdx.x;
    const int lane = tid & 127;    // float4 column 0..127
    const int psub = tid >> 7;     // 0..7

    // partial xsum over this sub-reducer's 16 chunks (coalesced across lanes)
    float4 acc = make_float4(0.f, 0.f, 0.f, 0.f);
    const float4* pp =
        reinterpret_cast<const float4*>(g_partials + ((size_t)b * NS + psub * PPS) * DD) + lane;
#pragma unroll
    for (int p = 0; p < PPS; ++p) {
        float4 v = pp[(size_t)p * (DD / 4)];
        acc.x += v.x; acc.y += v.y; acc.z += v.z; acc.w += v.w;
    }

    // fold the 16 c partials for this lane (L2-hot, 16 independent loads)
    float4 c4 = make_float4(0.f, 0.f, 0.f, 0.f);
    const float4* cp = reinterpret_cast<const float4*>(g_cpart) + lane;
#pragma unroll
    for (int j = 0; j < CBLKS; ++j) {
        float4 v = cp[(size_t)j * (DD / 4)];
        c4.x += v.x; c4.y += v.y; c4.z += v.z; c4.w += v.w;
    }

    float val = acc.x * c4.x + acc.y * c4.y + acc.z * c4.z + acc.w * c4.w;
    if (psub == 0) {               // bias term counted exactly once per lane
        const float4 br4 = reinterpret_cast<const float4*>(br)[lane];
        const float4 wl4 = reinterpret_cast<const float4*>(Wl)[lane];
        val += (float)SS * (br4.x * wl4.x + br4.y * wl4.y + br4.z * wl4.z + br4.w * wl4.w);
    }

    __shared__ float sdata[1024];
    sdata[tid] = val;
    __syncthreads();
#pragma unroll
    for (int off = 512; off > 0; off >>= 1) {
        if (tid < off) sdata[tid] += sdata[tid + off];
        __syncthreads();
    }
    if (tid == 0) {
        float z = sdata[0] + bl[0];
        out[b] = 1.0f / (1.0f + expf(-z));
    }
}

extern "C" void kernel_launch(void* const* d_in, const int* in_sizes, int n_in,
                              void* d_out, int out_size)
{
    // metadata order: x, Wq, bq, Wv, bv, Wr, br, Wl, bl
    const float* x  = (const float*)d_in[0];
    const float* Wr = (const float*)d_in[5];
    const float* br = (const float*)d_in[6];
    const float* Wl = (const float*)d_in[7];
    const float* bl = (const float*)d_in[8];
    float* out = (float*)d_out;

    k_reduce_and_c<<<BB * NS + CBLKS, 128>>>(x, Wr, Wl);
    k_finish<<<BB, 1024>>>(br, Wl, bl, out);
}

// round 4
// speedup vs baseline: 1.6912x; 1.3113x over previous
#include <cuda_runtime.h>

// LogLinearAttention — algebraic collapse (exact; rel_err=0 in R1/R2):
//   softmax over axis=1 then sum over axis=1 => attention columns sum to 1:
//     out[b] = sigmoid( xsum[b,:]·c + S*(br·Wl) + bl )
//   xsum[b,e] = sum_s x[b,s,e],  c[e] = sum_d Wl[d]*Wr[d,e].
//
// R3: the 8-block finisher was latency-bound on 8 SMs (11.9us). Split the
// finish into 128 one-wave dot blocks + a trivial final block.

#define BB 8
#define SS 2048
#define DD 512
#define NS 128                    // s-splits for the x reduction
#define ROWS_PER (SS / NS)        // 16 rows per block
#define CBLKS 16                  // d-split blocks for c partials
#define DCHUNK (DD / CBLKS)       // 32 d-rows per c-block
#define PB 16                     // dot blocks per batch
#define PPB (NS / PB)             // 8 partial vectors per dot block

__device__ float g_partials[BB * NS * DD];   // per-(b, s-chunk) partial row sums (2 MB)
__device__ float g_cpart[CBLKS * DD];        // partial c over d-chunks
__device__ float g_dots[BB * PB];            // per-block partial dot scalars

// ── K1: 1024 blocks reduce x over s; 16 extra blocks compute c partials ──
__global__ void __launch_bounds__(128) k_reduce_and_c(
    const float* __restrict__ x,
    const float* __restrict__ Wr,
    const float* __restrict__ Wl)
{
    const int blk = blockIdx.x;
    const int tid = threadIdx.x;   // 128 threads = one float4 lane each (D=512)

    if (blk < BB * NS) {
        const int b  = blk / NS;
        const int sc = blk % NS;
        const float4* xp =
            reinterpret_cast<const float4*>(x + ((size_t)b * SS + (size_t)sc * ROWS_PER) * DD) + tid;
        float4 acc = make_float4(0.f, 0.f, 0.f, 0.f);
#pragma unroll
        for (int s = 0; s < ROWS_PER; ++s) {            // 16 independent loads
            float4 v = xp[(size_t)s * (DD / 4)];
            acc.x += v.x; acc.y += v.y; acc.z += v.z; acc.w += v.w;
        }
        reinterpret_cast<float4*>(g_partials + (size_t)blk * DD)[tid] = acc;
    } else {
        // c partial: block j covers d in [j*32, j*32+32), all 512 e columns.
        const int j = blk - BB * NS;
        __shared__ float s_wl[DCHUNK];
        if (tid < DCHUNK) s_wl[tid] = Wl[j * DCHUNK + tid];
        __syncthreads();

        const float4* wr =
            reinterpret_cast<const float4*>(Wr + (size_t)j * DCHUNK * DD) + tid;
        float4 acc = make_float4(0.f, 0.f, 0.f, 0.f);
#pragma unroll
        for (int d = 0; d < DCHUNK; ++d) {              // 32 independent loads
            float4 w = wr[(size_t)d * (DD / 4)];
            float wl = s_wl[d];
            acc.x += wl * w.x; acc.y += wl * w.y; acc.z += wl * w.z; acc.w += wl * w.w;
        }
        reinterpret_cast<float4*>(g_cpart)[(size_t)j * (DD / 4) + tid] = acc;
    }
}

// ── K2: 128 blocks (one SM each): reduce 8 partial vectors, fold c, dot ──
__global__ void __launch_bounds__(128) k_dot()
{
    const int b   = blockIdx.x / PB;
    const int pb  = blockIdx.x % PB;
    const int tid = threadIdx.x;   // one float4 lane each

    // partial xsum over this block's 8 chunks
    float4 acc = make_float4(0.f, 0.f, 0.f, 0.f);
    const float4* pp =
        reinterpret_cast<const float4*>(g_partials + ((size_t)b * NS + pb * PPB) * DD) + tid;
#pragma unroll
    for (int p = 0; p < PPB; ++p) {
        float4 v = pp[(size_t)p * (DD / 4)];
        acc.x += v.x; acc.y += v.y; acc.z += v.z; acc.w += v.w;
    }

    // fold the 16 c partials for this lane (L2-hot)
    float4 c4 = make_float4(0.f, 0.f, 0.f, 0.f);
    const float4* cp = reinterpret_cast<const float4*>(g_cpart) + tid;
#pragma unroll
    for (int j = 0; j < CBLKS; ++j) {
        float4 v = cp[(size_t)j * (DD / 4)];
        c4.x += v.x; c4.y += v.y; c4.z += v.z; c4.w += v.w;
    }

    float val = acc.x * c4.x + acc.y * c4.y + acc.z * c4.z + acc.w * c4.w;

    // block-reduce 128 scalars: warp shfl then cross-warp via shared
#pragma unroll
    for (int off = 16; off > 0; off >>= 1)
        val += __shfl_down_sync(0xffffffffu, val, off);
    __shared__ float warp_s[4];
    if ((tid & 31) == 0) warp_s[tid >> 5] = val;
    __syncthreads();
    if (tid == 0)
        g_dots[blockIdx.x] = warp_s[0] + warp_s[1] + warp_s[2] + warp_s[3];
}

// ── K3: one tiny block: fold scalars + bias, sigmoid ──
__global__ void __launch_bounds__(128) k_final(
    const float* __restrict__ br,
    const float* __restrict__ Wl,
    const float* __restrict__ bl,
    float* __restrict__ out)
{
    const int tid = threadIdx.x;

    // bias dot: br·Wl across all 512 elements (4 per thread)
    const float4 br4 = reinterpret_cast<const float4*>(br)[tid];
    const float4 wl4 = reinterpret_cast<const float4*>(Wl)[tid];
    float bv = br4.x * wl4.x + br4.y * wl4.y + br4.z * wl4.z + br4.w * wl4.w;
#pragma unroll
    for (int off = 16; off > 0; off >>= 1)
        bv += __shfl_down_sync(0xffffffffu, bv, off);
    __shared__ float warp_s[4];
    __shared__ float s_bias;
    if ((tid & 31) == 0) warp_s[tid >> 5] = bv;
    __syncthreads();
    if (tid == 0) s_bias = warp_s[0] + warp_s[1] + warp_s[2] + warp_s[3];
    __syncthreads();

    // fold the 16 dot scalars per batch; tid -> (b = tid/16, j = tid%16)
    float d = g_dots[tid];                              // BB*PB = 128 scalars
#pragma unroll
    for (int off = 8; off > 0; off >>= 1)
        d += __shfl_down_sync(0xffffffffu, d, off, 16);
    if ((tid & 15) == 0) {
        const int b = tid >> 4;
        float z = d + (float)SS * s_bias + bl[0];
        out[b] = 1.0f / (1.0f + expf(-z));
    }
}

extern "C" void kernel_launch(void* const* d_in, const int* in_sizes, int n_in,
                              void* d_out, int out_size)
{
    // metadata order: x, Wq, bq, Wv, bv, Wr, br, Wl, bl
    const float* x  = (const float*)d_in[0];
    const float* Wr = (const float*)d_in[5];
    const float* br = (const float*)d_in[6];
    const float* Wl = (const float*)d_in[7];
    const float* bl = (const float*)d_in[8];
    float* out = (float*)d_out;

    k_reduce_and_c<<<BB * NS + CBLKS, 128>>>(x, Wr, Wl);
    k_dot<<<BB * PB, 128>>>();
    k_final<<<1, 128>>>(br, Wl, bl, out);
}

// round 5
// speedup vs baseline: 1.7293x; 1.0226x over previous
#include <cuda_runtime.h>

// LogLinearAttention — algebraic collapse (exact; rel_err=0 across R1-R3):
//   softmax over axis=1 then sum over axis=1 => attention columns sum to 1:
//     out[b] = sigmoid( sum_{s,e} x[b,s,e]*c[e] + S*(br·Wl) + bl )
//   c[e] = sum_d Wl[d]*Wr[d,e].  q/v projections are dead.
//
// R4: single streaming pass over x computing the dot directly (no xsum
// partials round-trip). 296 blocks = exactly 2/SM; low MLP_p1 (unroll 4,
// continuous) to avoid the cross-CTA L1tex-queue spread that capped R3's
// reducer at 3 TB/s.

#define BB 8
#define SS 2048
#define DD 512
#define DD4 (DD / 4)              // 128 float4 columns
#define CBLK_D 16                 // d-chunks for c partials
#define CBLK_E 8                  // e-chunks for c partials
#define DCH (DD / CBLK_D)         // 32 d rows per c-chunk
#define ECH4 (DD4 / CBLK_E)       // 16 float4 cols per c-chunk
#define JPB 37                    // row-range blocks per batch (8*37=296 = 2*148)
#define NBLK (BB * JPB)           // 296 main blocks

__device__ float g_cpart[CBLK_D * DD];  // c partials over d-chunks (32 KB)
__device__ float g_dots[NBLK];          // per-block partial dots

// ── k_c: 128 one-wave blocks compute c partials: cpart[jd][e] = sum_{d in chunk} Wl[d]*Wr[d,e]
__global__ void __launch_bounds__(128) k_c(
    const float* __restrict__ Wr,
    const float* __restrict__ Wl)
{
    const int jd = blockIdx.x / CBLK_E;       // d-chunk
    const int je = blockIdx.x % CBLK_E;       // e-chunk
    const int tf = threadIdx.x % ECH4;        // float4 col within chunk (0..15)
    const int td = threadIdx.x / ECH4;        // d-subgroup (0..7), 4 d's each

    const int e4 = je * ECH4 + tf;            // global float4 column
    float4 acc = make_float4(0.f, 0.f, 0.f, 0.f);
#pragma unroll
    for (int k = 0; k < DCH / 8; ++k) {       // 4 d rows per thread
        const int d = jd * DCH + td * (DCH / 8) + k;
        const float wl = __ldg(&Wl[d]);
        const float4 w = reinterpret_cast<const float4*>(Wr)[(size_t)d * DD4 + e4];
        acc.x += wl * w.x; acc.y += wl * w.y; acc.z += wl * w.z; acc.w += wl * w.w;
    }

    // fold the 8 d-subgroups via shared
    __shared__ float4 s_acc[8][ECH4];
    s_acc[td][tf] = acc;
    __syncthreads();
    if (td == 0) {
        float4 t = s_acc[0][tf];
#pragma unroll
        for (int i = 1; i < 8; ++i) {
            float4 v = s_acc[i][tf];
            t.x += v.x; t.y += v.y; t.z += v.z; t.w += v.w;
        }
        reinterpret_cast<float4*>(g_cpart)[(size_t)jd * DD4 + e4] = t;
    }
}

// ── k_main: 296 blocks x 256 thr; each block streams its row range of x and
//    accumulates the scalar dot with c. Thread = (r0 = tid/128, col = tid%128).
__global__ void __launch_bounds__(256) k_main(
    const float* __restrict__ x)
{
    const int blk = blockIdx.x;
    const int b   = blk / JPB;
    const int j   = blk % JPB;
    const int tid = threadIdx.x;
    const int col = tid & (DD4 - 1);          // float4 column 0..127
    const int r0  = tid >> 7;                 // 0 or 1

    // fold this column's c from the 16 d-chunk partials (L2-hot, 16 loads)
    float4 c4 = make_float4(0.f, 0.f, 0.f, 0.f);
#pragma unroll
    for (int jd = 0; jd < CBLK_D; ++jd) {
        float4 v = reinterpret_cast<const float4*>(g_cpart)[(size_t)jd * DD4 + col];
        c4.x += v.x; c4.y += v.y; c4.z += v.z; c4.w += v.w;
    }

    const int r_begin = (j * SS) / JPB;
    const int r_end   = ((j + 1) * SS) / JPB;
    const float4* xb  = reinterpret_cast<const float4*>(x + (size_t)b * SS * DD);

    float val = 0.f;
    int r = r_begin + r0;
#pragma unroll 4
    for (; r < r_end; r += 2) {               // continuous stream, MLP_p1 ~ 4
        float4 v = xb[(size_t)r * DD4 + col];
        val += v.x * c4.x + v.y * c4.y + v.z * c4.z + v.w * c4.w;
    }

    // block-reduce 256 scalars
#pragma unroll
    for (int off = 16; off > 0; off >>= 1)
        val += __shfl_down_sync(0xffffffffu, val, off);
    __shared__ float warp_s[8];
    if ((tid & 31) == 0) warp_s[tid >> 5] = val;
    __syncthreads();
    if (tid == 0) {
        float t = warp_s[0];
#pragma unroll
        for (int i = 1; i < 8; ++i) t += warp_s[i];
        g_dots[blk] = t;
    }
}

// ── k_final: fold 37 partial dots per batch + bias term, sigmoid ──
__global__ void __launch_bounds__(512) k_final(
    const float* __restrict__ br,
    const float* __restrict__ Wl,
    const float* __restrict__ bl,
    float* __restrict__ out)
{
    const int tid = threadIdx.x;
    __shared__ float warp_s[16];
    __shared__ float s_bias;

    // bias dot br·Wl over 512 elems: threads 0..127, float4 each
    if (tid < 128) {
        const float4 br4 = reinterpret_cast<const float4*>(br)[tid];
        const float4 wl4 = reinterpret_cast<const float4*>(Wl)[tid];
        float bv = br4.x * wl4.x + br4.y * wl4.y + br4.z * wl4.z + br4.w * wl4.w;
#pragma unroll
        for (int off = 16; off > 0; off >>= 1)
            bv += __shfl_down_sync(0xffffffffu, bv, off);
        if ((tid & 31) == 0) warp_s[tid >> 5] = bv;
    }
    __syncthreads();
    if (tid == 0) s_bias = warp_s[0] + warp_s[1] + warp_s[2] + warp_s[3];
    __syncthreads();

    // per-b fold: 64-thread group per batch, i<37 valid
    const int b = tid >> 6;
    const int i = tid & 63;
    float d = (i < JPB) ? g_dots[b * JPB + i] : 0.f;
#pragma unroll
    for (int off = 16; off > 0; off >>= 1)
        d += __shfl_down_sync(0xffffffffu, d, off);
    __shared__ float half_s[16];                 // two warps per group
    if ((tid & 31) == 0) half_s[tid >> 5] = d;
    __syncthreads();
    if (i == 0) {
        float z = half_s[(tid >> 5)] + half_s[(tid >> 5) + 1] + (float)SS * s_bias + bl[0];
        out[b] = 1.0f / (1.0f + expf(-z));
    }
}

extern "C" void kernel_launch(void* const* d_in, const int* in_sizes, int n_in,
                              void* d_out, int out_size)
{
    // metadata order: x, Wq, bq, Wv, bv, Wr, br, Wl, bl
    const float* x  = (const float*)d_in[0];
    const float* Wr = (const float*)d_in[5];
    const float* br = (const float*)d_in[6];
    const float* Wl = (const float*)d_in[7];
    const float* bl = (const float*)d_in[8];
    float* out = (float*)d_out;

    k_c<<<CBLK_D * CBLK_E, 128>>>(Wr, Wl);
    k_main<<<NBLK, 256>>>(x);
    k_final<<<1, 512>>>(br, Wl, bl, out);
}